// round 3
// baseline (speedup 1.0000x reference)
#include <cuda_runtime.h>
#include <cuda_bf16.h>

// Chebyshev (L-inf) pairwise distance: out[i,j] = max_d |A[i,d] - B[j,d]|
// A: [4096, 32] fp32, B: [4096, 32] fp32, out: [4096, 4096] fp32.
//
// R3: Blackwell packed-fp32x2 math. B is stored NEGATED in smem so the
// subtract becomes add.rn.f32x2 (one FADD2 yields two diffs, fma pipe).
// A is stored DUPLICATED ((a,a) pairs) so the packed operand comes straight
// from an LDS broadcast. FMNMX with |src| modifier consumes the pair halves
// directly -> exactly 1 alu-pipe instruction per output*d (the floor).

constexpr int D    = 32;
constexpr int TILE = 128;

__global__ __launch_bounds__(512, 2)
void cheby_kernel(const float* __restrict__ A, const float* __restrict__ B,
                  float* __restrict__ out, int M) {
    __shared__ float Adup[D][2 * TILE];   // Adup[d][2r], [2r+1] = A[bi+r][d]
    __shared__ float Bs[D][TILE];         // Bs[d][c] = -B[bj+c][d]

    const int tid = threadIdx.x;
    const int bi  = blockIdx.y * TILE;
    const int bj  = blockIdx.x * TILE;

    // Tile load + transpose. 1024 float4 per input tile, 512 threads x 2.
    #pragma unroll
    for (int k = 0; k < 2; k++) {
        int idx = tid + k * 512;        // float4 index 0..1023
        int row = idx >> 3;             // 8 float4 per 32-wide row
        int dg  = (idx & 7) << 2;
        float4 va = *reinterpret_cast<const float4*>(A + (size_t)(bi + row) * D + dg);
        Adup[dg + 0][2*row] = va.x; Adup[dg + 0][2*row + 1] = va.x;
        Adup[dg + 1][2*row] = va.y; Adup[dg + 1][2*row + 1] = va.y;
        Adup[dg + 2][2*row] = va.z; Adup[dg + 2][2*row + 1] = va.z;
        Adup[dg + 3][2*row] = va.w; Adup[dg + 3][2*row + 1] = va.w;
        float4 vb = *reinterpret_cast<const float4*>(B + (size_t)(bj + row) * D + dg);
        Bs[dg + 0][row] = -vb.x; Bs[dg + 1][row] = -vb.y;
        Bs[dg + 2][row] = -vb.z; Bs[dg + 3][row] = -vb.w;
    }
    __syncthreads();

    const int tx = tid & 31;            // 32 x 4 cols = 128
    const int ty = tid >> 5;            // 16 x 8 rows = 128
    const int ri = ty * 8;
    const int rj = tx * 4;

    float acc[8][4];
    #pragma unroll
    for (int i = 0; i < 8; i++)
        #pragma unroll
        for (int j = 0; j < 4; j++)
            acc[i][j] = 0.0f;           // |diff| >= 0, so 0 is a safe identity

    #pragma unroll 4
    for (int d = 0; d < D; d++) {
        // 8 duplicated-a pairs (a_i, a_i): 64B, broadcast within the warp.
        const ulonglong2* ap = reinterpret_cast<const ulonglong2*>(&Adup[d][2 * ri]);
        ulonglong2 a01 = ap[0], a23 = ap[1], a45 = ap[2], a67 = ap[3];
        unsigned long long ad[8] = {a01.x, a01.y, a23.x, a23.y,
                                    a45.x, a45.y, a67.x, a67.y};
        // 4 negated-b values as two natural pairs (nb0,nb1), (nb2,nb3).
        ulonglong2 bq = *reinterpret_cast<const ulonglong2*>(&Bs[d][rj]);

        #pragma unroll
        for (int i = 0; i < 8; i++) {
            unsigned long long d0, d1;
            asm("add.rn.f32x2 %0, %1, %2;" : "=l"(d0) : "l"(ad[i]), "l"(bq.x));
            asm("add.rn.f32x2 %0, %1, %2;" : "=l"(d1) : "l"(ad[i]), "l"(bq.y));
            float l0, h0, l1, h1;
            asm("mov.b64 {%0, %1}, %2;" : "=f"(l0), "=f"(h0) : "l"(d0));
            asm("mov.b64 {%0, %1}, %2;" : "=f"(l1), "=f"(h1) : "l"(d1));
            acc[i][0] = fmaxf(acc[i][0], fabsf(l0));
            acc[i][1] = fmaxf(acc[i][1], fabsf(h0));
            acc[i][2] = fmaxf(acc[i][2], fabsf(l1));
            acc[i][3] = fmaxf(acc[i][3], fabsf(h1));
        }
    }

    #pragma unroll
    for (int i = 0; i < 8; i++) {
        float* p = out + (size_t)(bi + ri + i) * M + (bj + rj);
        *reinterpret_cast<float4*>(p) =
            make_float4(acc[i][0], acc[i][1], acc[i][2], acc[i][3]);
    }
}

extern "C" void kernel_launch(void* const* d_in, const int* in_sizes, int n_in,
                              void* d_out, int out_size) {
    const float* A = (const float*)d_in[0];
    const float* B = (const float*)d_in[1];
    float* out = (float*)d_out;
    int N = in_sizes[0] / D;   // 4096
    int M = in_sizes[1] / D;   // 4096
    dim3 grid(M / TILE, N / TILE);
    cheby_kernel<<<grid, 512>>>(A, B, out, M);
}